// round 3
// baseline (speedup 1.0000x reference)
#include <cuda_runtime.h>
#include <cstdint>

#define C_MAX   256
#define N_MAX   65536
#define D_MAXEL 4096
#define BETA    0.3f
#define PA_ROWS 64

// -------- device scratch (static: no allocations allowed) --------
__device__ float g_sums[(size_t)C_MAX * D_MAXEL]; // class sums (raw; divided on the fly)
__device__ int   g_counts[C_MAX];
__device__ int   g_fill[C_MAX];
__device__ int   g_off[C_MAX + 1];
__device__ int   g_idx[N_MAX];    // sample index sorted by class
__device__ int   g_slab[N_MAX];   // label at sorted position
__device__ float g_d[N_MAX];      // per-sample squared distance, SORTED order
__device__ int   g_npres;
__device__ int   g_is64;          // labels are int64?
__device__ int   g_C;

__device__ __forceinline__ int get_label(const void* labels, int i, int is64) {
    if (is64) return (int)((const long long*)labels)[i];
    return ((const int*)labels)[i];
}

// -------- kernels --------

// Zero the class-sum region (C_MAX * D floats).
__global__ void k_zero(int total4) {
    int idx = blockIdx.x * blockDim.x + threadIdx.x;
    if (idx < total4) ((float4*)g_sums)[idx] = make_float4(0.f, 0.f, 0.f, 0.f);
}

// Single block: dtype detect + histogram + exclusive scan + n_present.
__global__ void k_prep(const void* labels, const void* ncls, int N) {
    __shared__ int h[C_MAX];
    __shared__ int tmp[C_MAX];
    __shared__ int ok;
    __shared__ int np;
    int t = threadIdx.x;                       // blockDim.x == 1024

    if (t == 0) { ok = 1; np = 0; }
    for (int i = t; i < C_MAX; i += blockDim.x) h[i] = 0;
    __syncthreads();

    // dtype detect: sample odd 32-bit words; int32 labels -> odd words are labels
    // (uniform in [0,C)), so all-zero over 2048 samples ~ impossible.
    {
        const int* w = (const int*)labels;
        int half = N / 2;
        int samples = half < 2048 ? half : 2048;
        int stride = samples > 0 ? half / samples : 1;
        int bad = 0;
        for (int s = t; s < samples; s += blockDim.x)
            if (w[2 * s * stride + 1] != 0) bad = 1;
        if (bad) ok = 0;
    }
    __syncthreads();
    int is64 = ok;
    if (t == 0) {
        g_is64 = is64;
        int c = 100;
        if (ncls) c = ((const int*)ncls)[0];
        if (c < 1 || c > C_MAX) c = 100;
        g_C = c;
    }

    // histogram
    for (int i = t; i < N; i += blockDim.x) {
        int l = get_label(labels, i, is64);
        atomicAdd(&h[l], 1);
    }
    __syncthreads();

    // n_present
    if (t < C_MAX && h[t] > 0) atomicAdd(&np, 1);

    // inclusive scan (Hillis-Steele) on first C_MAX lanes
    int v = (t < C_MAX) ? h[t] : 0;
    if (t < C_MAX) tmp[t] = v;
    __syncthreads();
    #pragma unroll
    for (int o = 1; o < C_MAX; o <<= 1) {
        int x = (t < C_MAX && t >= o) ? tmp[t - o] : 0;
        __syncthreads();
        if (t < C_MAX) tmp[t] += x;
        __syncthreads();
    }
    if (t < C_MAX) {
        int excl = tmp[t] - v;
        g_counts[t] = v;
        g_off[t] = excl;
        g_fill[t] = excl;
        if (t == C_MAX - 1) g_off[C_MAX] = tmp[t];
    }
    if (t == 0) g_npres = np;
}

__global__ void k_scatter(const void* labels, int N) {
    __shared__ int base[C_MAX];
    __shared__ int cnt1[C_MAX];
    __shared__ int cnt2[C_MAX];
    for (int i = threadIdx.x; i < C_MAX; i += blockDim.x) { cnt1[i] = 0; cnt2[i] = 0; }
    __syncthreads();
    int is64 = g_is64;
    int i = blockIdx.x * blockDim.x + threadIdx.x;
    int l = -1;
    if (i < N) {
        l = get_label(labels, i, is64);
        atomicAdd(&cnt1[l], 1);
    }
    __syncthreads();
    for (int c = threadIdx.x; c < C_MAX; c += blockDim.x)
        if (cnt1[c]) base[c] = atomicAdd(&g_fill[c], cnt1[c]);
    __syncthreads();
    if (i < N) {
        int r = atomicAdd(&cnt2[l], 1);
        int pos = base[l] + r;
        g_idx[pos] = i;
        g_slab[pos] = l;
    }
}

// Pass A: class sums over class-sorted rows, float4 per thread.
// Register accumulation across a run of same-class rows, flush on change.
__global__ void k_sums(const float4* __restrict__ emb, int N, int D4) {
    int col = blockIdx.y * blockDim.x + threadIdx.x; // float4 column
    if (col >= D4) return;
    int D = D4 * 4;
    int p0 = blockIdx.x * PA_ROWS;
    int p1 = min(p0 + PA_ROWS, N);
    int cur = -1;
    float4 acc = make_float4(0.f, 0.f, 0.f, 0.f);
    for (int p = p0; p < p1; p++) {
        int c = g_slab[p];
        if (c != cur) {
            if (cur >= 0) {
                float* dst = &g_sums[(size_t)cur * D + col * 4];
                atomicAdd(dst + 0, acc.x);
                atomicAdd(dst + 1, acc.y);
                atomicAdd(dst + 2, acc.z);
                atomicAdd(dst + 3, acc.w);
            }
            cur = c;
            acc = make_float4(0.f, 0.f, 0.f, 0.f);
        }
        long long i = g_idx[p];
        float4 v = emb[i * (long long)D4 + col];
        acc.x += v.x; acc.y += v.y; acc.z += v.z; acc.w += v.w;
    }
    if (cur >= 0) {
        float* dst = &g_sums[(size_t)cur * D + col * 4];
        atomicAdd(dst + 0, acc.x);
        atomicAdd(dst + 1, acc.y);
        atomicAdd(dst + 2, acc.z);
        atomicAdd(dst + 3, acc.w);
    }
}

// Pass B: per-sample squared distance to class centroid (sums * 1/cnt inline).
// One warp per SORTED position; writes g_d in sorted order.
__global__ void k_dist(const float4* __restrict__ emb, int N, int D4) {
    int w = threadIdx.x >> 5, lane = threadIdx.x & 31;
    int p = blockIdx.x * (blockDim.x >> 5) + w;
    if (p >= N) return;
    int l = g_slab[p];
    long long i = g_idx[p];
    float inv = 1.f / (float)max(g_counts[l], 1);
    const float4* e = emb + i * (long long)D4;
    const float4* c = (const float4*)g_sums + (size_t)l * D4;
    float s = 0.f;
    for (int k = lane; k < D4; k += 32) {
        float4 a = e[k];
        float4 b = c[k];
        float dx = a.x - b.x * inv;
        float dy = a.y - b.y * inv;
        float dz = a.z - b.z * inv;
        float dw = a.w - b.w * inv;
        s = fmaf(dx, dx, s);
        s = fmaf(dy, dy, s);
        s = fmaf(dz, dz, s);
        s = fmaf(dw, dw, s);
    }
    #pragma unroll
    for (int o = 16; o; o >>= 1) s += __shfl_down_sync(0xffffffffu, s, o);
    if (lane == 0) g_d[p] = s;
}

// Single block: per-class unbiased variance of d (contiguous runs), final output.
__global__ void k_var(float* out) {
    __shared__ float sh_loss;
    int t = threadIdx.x;
    int warp = t >> 5, lane = t & 31;
    int nwarps = blockDim.x >> 5;
    if (t == 0) sh_loss = 0.f;
    __syncthreads();
    int C = g_C;
    for (int c = warp; c < C; c += nwarps) {
        int cnt = g_counts[c];
        if (cnt < 2) continue;
        int o = g_off[c];
        float s = 0.f;
        for (int p = o + lane; p < o + cnt; p += 32) s += g_d[p];
        #pragma unroll
        for (int q = 16; q; q >>= 1) s += __shfl_xor_sync(0xffffffffu, s, q);
        float mean = s / (float)cnt;
        float v = 0.f;
        for (int p = o + lane; p < o + cnt; p += 32) {
            float dv = g_d[p] - mean;
            v = fmaf(dv, dv, v);
        }
        #pragma unroll
        for (int q = 16; q; q >>= 1) v += __shfl_xor_sync(0xffffffffu, v, q);
        if (lane == 0) atomicAdd(&sh_loss, v / (float)(cnt - 1));
    }
    __syncthreads();
    if (t == 0) {
        float np = (float)max(g_npres, 1);
        out[0] = BETA * sh_loss / np;
    }
}

// -------- launch --------
extern "C" void kernel_launch(void* const* d_in, const int* in_sizes, int n_in,
                              void* d_out, int out_size) {
    const float* emb = (const float*)d_in[0];
    const void*  lab = d_in[1];
    const void*  ncl = (n_in >= 3) ? d_in[2] : nullptr;
    float* out = (float*)d_out;

    int N = in_sizes[1];
    int D = in_sizes[0] / N;
    int D4 = D / 4;                       // D multiple of 4 for this problem
    int total4 = C_MAX * D4;

    k_zero<<<(total4 + 255) / 256, 256>>>(total4);
    k_prep<<<1, 1024>>>(lab, ncl, N);
    k_scatter<<<(N + 255) / 256, 256>>>(lab, N);

    dim3 gA((N + PA_ROWS - 1) / PA_ROWS, (D4 + 255) / 256);
    k_sums<<<gA, 256>>>((const float4*)emb, N, D4);

    int wpb = 8; // warps per block
    k_dist<<<(N + wpb - 1) / wpb, wpb * 32>>>((const float4*)emb, N, D4);
    k_var<<<1, 1024>>>(out);
}

// round 5
// speedup vs baseline: 1.3564x; 1.3564x over previous
#include <cuda_runtime.h>
#include <cstdint>

#define C_MAX   256
#define N_MAX   65536
#define D_MAXEL 4096
#define BETA    0.3f
#define PA_ROWS 32

// -------- device scratch (static: no allocations allowed) --------
__device__ float g_sums[(size_t)C_MAX * D_MAXEL]; // class sums (raw; divided on the fly)
__device__ int   g_counts[C_MAX];
__device__ int   g_fill[C_MAX];
__device__ int   g_off[C_MAX + 1];
__device__ int   g_idx[N_MAX];    // sample index sorted by class
__device__ int   g_slab[N_MAX];   // label at sorted position
__device__ float g_d[N_MAX];      // per-sample squared distance, SORTED order
__device__ int   g_npres;
__device__ int   g_is64;          // labels are int64?
__device__ int   g_C;

__device__ __forceinline__ int get_label(const void* labels, int i, int is64) {
    if (is64) return (int)((const long long*)labels)[i];
    return ((const int*)labels)[i];
}

// -------- kernels --------

// Zero class sums + counts; block 0 additionally does dtype detect + num_classes.
__global__ void k_zero(const void* labels, const void* ncls, int N, int total4) {
    int idx = blockIdx.x * blockDim.x + threadIdx.x;
    if (idx < total4) ((float4*)g_sums)[idx] = make_float4(0.f, 0.f, 0.f, 0.f);
    if (idx < C_MAX) g_counts[idx] = 0;
    if (blockIdx.x == 0) {
        // dtype detect: sample odd 32-bit words; if labels were int32, odd words
        // are labels themselves (uniform in [0,C)) -> all-zero is impossible.
        __shared__ int ok;
        if (threadIdx.x == 0) ok = 1;
        __syncthreads();
        const int* w = (const int*)labels;
        int half = N / 2;
        int samples = half < 2048 ? half : 2048;
        int stride = samples > 0 ? half / samples : 1;
        int bad = 0;
        for (int s = threadIdx.x; s < samples; s += blockDim.x)
            if (w[2 * s * stride + 1] != 0) bad = 1;
        if (bad) ok = 0;
        __syncthreads();
        if (threadIdx.x == 0) {
            g_is64 = ok;
            int c = 100;
            if (ncls) c = ((const int*)ncls)[0];
            if (c < 1 || c > C_MAX) c = 100;
            g_C = c;
        }
    }
}

// Multi-block histogram into g_counts.
__global__ void k_hist(const void* labels, int N) {
    __shared__ int h[C_MAX];
    for (int i = threadIdx.x; i < C_MAX; i += blockDim.x) h[i] = 0;
    __syncthreads();
    int is64 = g_is64;
    for (int i = blockIdx.x * blockDim.x + threadIdx.x; i < N; i += gridDim.x * blockDim.x) {
        int l = get_label(labels, i, is64);
        atomicAdd(&h[l], 1);
    }
    __syncthreads();
    for (int i = threadIdx.x; i < C_MAX; i += blockDim.x)
        if (h[i]) atomicAdd(&g_counts[i], h[i]);
}

// One block (C_MAX threads): exclusive scan + n_present.
__global__ void k_scan() {
    __shared__ int tmp[C_MAX];
    __shared__ int np;
    int t = threadIdx.x;
    if (t == 0) np = 0;
    int v = g_counts[t];
    tmp[t] = v;
    __syncthreads();
    if (v > 0) atomicAdd(&np, 1);
    #pragma unroll
    for (int o = 1; o < C_MAX; o <<= 1) {
        int x = (t >= o) ? tmp[t - o] : 0;
        __syncthreads();
        tmp[t] += x;
        __syncthreads();
    }
    int excl = tmp[t] - v;
    g_off[t] = excl;
    g_fill[t] = excl;
    if (t == C_MAX - 1) g_off[C_MAX] = tmp[t];
    if (t == 0) g_npres = np;
}

__global__ void k_scatter(const void* labels, int N) {
    __shared__ int base[C_MAX];
    __shared__ int cnt1[C_MAX];
    __shared__ int cnt2[C_MAX];
    for (int i = threadIdx.x; i < C_MAX; i += blockDim.x) { cnt1[i] = 0; cnt2[i] = 0; }
    __syncthreads();
    int is64 = g_is64;
    int i = blockIdx.x * blockDim.x + threadIdx.x;
    int l = -1;
    if (i < N) {
        l = get_label(labels, i, is64);
        atomicAdd(&cnt1[l], 1);
    }
    __syncthreads();
    for (int c = threadIdx.x; c < C_MAX; c += blockDim.x)
        if (cnt1[c]) base[c] = atomicAdd(&g_fill[c], cnt1[c]);
    __syncthreads();
    if (i < N) {
        int r = atomicAdd(&cnt2[l], 1);
        int pos = base[l] + r;
        g_idx[pos] = i;
        g_slab[pos] = l;
    }
}

// Pass A: class sums over class-sorted rows, float4 per thread.
// Run boundaries precomputed in shared -> branch-free inner loop -> MLP.
__global__ void k_sums(const float4* __restrict__ emb, int N, int D4) {
    __shared__ int s_idx[PA_ROWS];
    __shared__ int s_run[PA_ROWS + 1];
    __shared__ int s_cls[PA_ROWS];
    __shared__ int s_nruns;

    int p0 = blockIdx.x * PA_ROWS;
    int n = min(PA_ROWS, N - p0);
    if (threadIdx.x < n) s_idx[threadIdx.x] = g_idx[p0 + threadIdx.x];
    if (threadIdx.x == 0) {
        int nr = 0, cur = -1;
        for (int j = 0; j < n; j++) {
            int c = g_slab[p0 + j];
            if (c != cur) { s_run[nr] = j; s_cls[nr] = c; nr++; cur = c; }
        }
        s_run[nr] = n;
        s_nruns = nr;
    }
    __syncthreads();

    int col = blockIdx.y * blockDim.x + threadIdx.x; // float4 column
    if (col >= D4) return;
    int D = D4 * 4;
    int nruns = s_nruns;
    for (int r = 0; r < nruns; r++) {
        int a = s_run[r], b = s_run[r + 1];
        float4 acc = make_float4(0.f, 0.f, 0.f, 0.f);
        #pragma unroll 4
        for (int j = a; j < b; j++) {
            float4 v = emb[(size_t)s_idx[j] * D4 + col];
            acc.x += v.x; acc.y += v.y; acc.z += v.z; acc.w += v.w;
        }
        float* dst = &g_sums[(size_t)s_cls[r] * D + col * 4];
        atomicAdd(dst + 0, acc.x);
        atomicAdd(dst + 1, acc.y);
        atomicAdd(dst + 2, acc.z);
        atomicAdd(dst + 3, acc.w);
    }
}

// Pass B: per-sample squared distance to class centroid (sums * 1/cnt inline).
// One warp per SORTED position; exact-trip-count unrolled loop for MLP.
__global__ void k_dist(const float4* __restrict__ emb, int N, int D4) {
    int w = threadIdx.x >> 5, lane = threadIdx.x & 31;
    int p = blockIdx.x * (blockDim.x >> 5) + w;
    if (p >= N) return;
    int l = g_slab[p];
    long long i = g_idx[p];
    float inv = 1.f / (float)max(g_counts[l], 1);
    const float4* e = emb + i * (long long)D4 + lane;
    const float4* c = (const float4*)g_sums + (size_t)l * D4 + lane;
    int iters = D4 >> 5; // D4 multiple of 32 for this problem
    float s = 0.f;
    #pragma unroll 4
    for (int t = 0; t < iters; t++) {
        float4 a = e[t * 32];
        float4 b = c[t * 32];
        float dx = a.x - b.x * inv;
        float dy = a.y - b.y * inv;
        float dz = a.z - b.z * inv;
        float dw = a.w - b.w * inv;
        s = fmaf(dx, dx, s);
        s = fmaf(dy, dy, s);
        s = fmaf(dz, dz, s);
        s = fmaf(dw, dw, s);
    }
    #pragma unroll
    for (int o = 16; o; o >>= 1) s += __shfl_down_sync(0xffffffffu, s, o);
    if (lane == 0) g_d[p] = s;
}

// Single block: per-class unbiased variance of d (contiguous runs), final output.
__global__ void k_var(float* out) {
    __shared__ float sh_loss;
    int t = threadIdx.x;
    int warp = t >> 5, lane = t & 31;
    int nwarps = blockDim.x >> 5;
    if (t == 0) sh_loss = 0.f;
    __syncthreads();
    int C = g_C;
    for (int c = warp; c < C; c += nwarps) {
        int cnt = g_counts[c];
        if (cnt < 2) continue;
        int o = g_off[c];
        float s = 0.f;
        for (int p = o + lane; p < o + cnt; p += 32) s += g_d[p];
        #pragma unroll
        for (int q = 16; q; q >>= 1) s += __shfl_xor_sync(0xffffffffu, s, q);
        float mean = s / (float)cnt;
        float v = 0.f;
        for (int p = o + lane; p < o + cnt; p += 32) {
            float dv = g_d[p] - mean;
            v = fmaf(dv, dv, v);
        }
        #pragma unroll
        for (int q = 16; q; q >>= 1) v += __shfl_xor_sync(0xffffffffu, v, q);
        if (lane == 0) atomicAdd(&sh_loss, v / (float)(cnt - 1));
    }
    __syncthreads();
    if (t == 0) {
        float np = (float)max(g_npres, 1);
        out[0] = BETA * sh_loss / np;
    }
}

// -------- launch --------
extern "C" void kernel_launch(void* const* d_in, const int* in_sizes, int n_in,
                              void* d_out, int out_size) {
    const float* emb = (const float*)d_in[0];
    const void*  lab = d_in[1];
    const void*  ncl = (n_in >= 3) ? d_in[2] : nullptr;
    float* out = (float*)d_out;

    int N = in_sizes[1];
    int D = in_sizes[0] / N;
    int D4 = D / 4;                       // D multiple of 4 for this problem
    int total4 = C_MAX * D4;

    k_zero<<<(total4 + 255) / 256, 256>>>(lab, ncl, N, total4);
    k_hist<<<64, 256>>>(lab, N);
    k_scan<<<1, C_MAX>>>();
    k_scatter<<<(N + 255) / 256, 256>>>(lab, N);

    dim3 gA((N + PA_ROWS - 1) / PA_ROWS, (D4 + 255) / 256);
    k_sums<<<gA, 256>>>((const float4*)emb, N, D4);

    int wpb = 8; // warps per block
    k_dist<<<(N + wpb - 1) / wpb, wpb * 32>>>((const float4*)emb, N, D4);
    k_var<<<1, 1024>>>(out);
}